// round 15
// baseline (speedup 1.0000x reference)
#include <cuda_runtime.h>
#include <cuda_fp16.h>
#include <cstdint>

#define TSEQ 2048
#define BATCH 8
#define DM 1024
#define HD 128
#define MTOT (BATCH * TSEQ)

// fp16 scratch: Q (pre-scaled by 1/sqrt(HD)), K, V.
__device__ __align__(16) __half g_qh[MTOT * HD];
__device__ __align__(16) __half g_kh[MTOT * HD];
__device__ __align__(16) __half g_vh[MTOT * HD];

__device__ __forceinline__ uint32_t smem_u32(const void* p) {
  return (uint32_t)__cvta_generic_to_shared(p);
}

__device__ __forceinline__ void mma_fp16(float* d, const uint32_t* a,
                                         const uint32_t* b) {
  asm volatile(
      "mma.sync.aligned.m16n8k16.row.col.f32.f16.f16.f32 "
      "{%0,%1,%2,%3}, {%4,%5,%6,%7}, {%8,%9}, {%0,%1,%2,%3};\n"
      : "+f"(d[0]), "+f"(d[1]), "+f"(d[2]), "+f"(d[3])
      : "r"(a[0]), "r"(a[1]), "r"(a[2]), "r"(a[3]), "r"(b[0]), "r"(b[1]));
}

__device__ __forceinline__ void ldm_x4(uint32_t* r, uint32_t addr) {
  asm volatile(
      "ldmatrix.sync.aligned.m8n8.x4.shared.b16 {%0,%1,%2,%3}, [%4];"
      : "=r"(r[0]), "=r"(r[1]), "=r"(r[2]), "=r"(r[3]) : "r"(addr));
}
__device__ __forceinline__ void ldm_x4_t(uint32_t* r, uint32_t addr) {
  asm volatile(
      "ldmatrix.sync.aligned.m8n8.x4.trans.shared.b16 {%0,%1,%2,%3}, [%4];"
      : "=r"(r[0]), "=r"(r[1]), "=r"(r[2]), "=r"(r[3]) : "r"(addr));
}

#define CP16(dst, src) \
  asm volatile("cp.async.cg.shared.global [%0], [%1], 16;" :: "r"(dst), "l"(src))
#define CP_COMMIT() asm volatile("cp.async.commit_group;" ::: "memory")
#define CP_WAIT0() asm volatile("cp.async.wait_group 0;" ::: "memory")
#define CP_WAIT1() asm volatile("cp.async.wait_group 1;" ::: "memory")

// 8 fp32 -> 8 fp16 (single)
__device__ __forceinline__ uint4 cvt8s(float4 a0, float4 a1) {
  __half2 h0 = __floats2half2_rn(a0.x, a0.y);
  __half2 h1 = __floats2half2_rn(a0.z, a0.w);
  __half2 h2 = __floats2half2_rn(a1.x, a1.y);
  __half2 h3 = __floats2half2_rn(a1.z, a1.w);
  return make_uint4(*(uint32_t*)&h0, *(uint32_t*)&h1, *(uint32_t*)&h2,
                    *(uint32_t*)&h3);
}

// ---------------------------------------------------------------------------
// Kernel 1: QKV projection (R13 measured-good, 93.4us). Uniform fp16 HMMA:
// y = xh * W. Grid (128,3), 512 thr, BK=32, double-buffered smem, 80B stride.
// ---------------------------------------------------------------------------
#define RSTRIDE 80
#define TILE_B (128 * RSTRIDE)  // 10240
#define NBUF_B (2 * TILE_B)     // Xh, W

__global__ __launch_bounds__(512) void qkv_hmma(
    const float* __restrict__ x, const float* __restrict__ Wq,
    const float* __restrict__ Wk, const float* __restrict__ Wv) {
  extern __shared__ __align__(1024) char smem[];
  const int yid = blockIdx.y;
  const float* W = (yid == 0) ? Wq : (yid == 1 ? Wk : Wv);

  const int tid = threadIdx.x;
  const int lane = tid & 31, wid = tid >> 5;
  const int wm = wid >> 2, wn = wid & 3;
  const int m0 = blockIdx.x * 128;
  const uint32_t sb = smem_u32(smem);

  const int lrow = tid >> 2, lc = tid & 3;
  const float* aSrc = x + (size_t)(m0 + lrow) * DM + lc * 8;
  const float* bSrc = W + (size_t)lrow * DM + lc * 8;
  const uint32_t stoOff = lrow * RSTRIDE + lc * 16;

  const uint32_t aColOff = (lane >> 4) * 16;
  const uint32_t aRowB = (wm * 32 + (lane & 15)) * RSTRIDE;
  const uint32_t bRowB = (wn * 32 + ((lane >> 4) << 3) + (lane & 7)) * RSTRIDE;
  const uint32_t bColOff = ((lane >> 3) & 1) * 16;

  float acc[2][4][4];
#pragma unroll
  for (int i = 0; i < 2; i++)
#pragma unroll
    for (int j = 0; j < 4; j++)
#pragma unroll
      for (int r = 0; r < 4; r++) acc[i][j][r] = 0.f;

  float4 pA0, pA1, pB0, pB1;
  pA0 = *(const float4*)(aSrc);
  pA1 = *(const float4*)(aSrc + 4);
  pB0 = *(const float4*)(bSrc);
  pB1 = *(const float4*)(bSrc + 4);
  {
    char* p = smem + stoOff;
    *(uint4*)(p) = cvt8s(pA0, pA1);
    *(uint4*)(p + TILE_B) = cvt8s(pB0, pB1);
  }
  __syncthreads();

  for (int kt = 0; kt < 32; kt++) {
    if (kt < 31) {
      const float* a = aSrc + (kt + 1) * 32;
      const float* b = bSrc + (kt + 1) * 32;
      pA0 = *(const float4*)(a);
      pA1 = *(const float4*)(a + 4);
      pB0 = *(const float4*)(b);
      pB1 = *(const float4*)(b + 4);
    }
    const uint32_t bufBase = sb + (kt & 1) * NBUF_B;
#pragma unroll
    for (int s = 0; s < 2; s++) {
      uint32_t ah[2][4], b2[2][4];
#pragma unroll
      for (int i = 0; i < 2; i++)
        ldm_x4(ah[i], bufBase + aRowB + i * (16 * RSTRIDE) + s * 32 + aColOff);
#pragma unroll
      for (int j = 0; j < 2; j++)
        ldm_x4(b2[j], bufBase + TILE_B + bRowB + j * (16 * RSTRIDE) + s * 32 + bColOff);
#pragma unroll
      for (int i = 0; i < 2; i++)
#pragma unroll
        for (int jj = 0; jj < 4; jj++)
          mma_fp16(acc[i][jj], ah[i], &b2[jj >> 1][(jj & 1) * 2]);
    }
    if (kt < 31) {
      char* p = smem + ((kt + 1) & 1) * NBUF_B + stoOff;
      *(uint4*)(p) = cvt8s(pA0, pA1);
      *(uint4*)(p + TILE_B) = cvt8s(pB0, pB1);
    }
    __syncthreads();
  }

  const int g = lane >> 2, tig = lane & 3;
  const float qs = (yid == 0) ? 0.08838834764831845f : 1.0f;
  __half* oh = (yid == 0) ? g_qh : (yid == 1 ? g_kh : g_vh);
#pragma unroll
  for (int i = 0; i < 2; i++) {
    int r0 = m0 + wm * 32 + i * 16 + g;
#pragma unroll
    for (int jj = 0; jj < 4; jj++) {
      int col = wn * 32 + jj * 8 + 2 * tig;
      __half2 h01 = __floats2half2_rn(acc[i][jj][0] * qs, acc[i][jj][1] * qs);
      __half2 h23 = __floats2half2_rn(acc[i][jj][2] * qs, acc[i][jj][3] * qs);
      *(uint32_t*)&oh[(size_t)r0 * HD + col] = *(uint32_t*)&h01;
      *(uint32_t*)&oh[(size_t)(r0 + 8) * HD + col] = *(uint32_t*)&h23;
    }
  }
}

// ---------------------------------------------------------------------------
// Kernel 2: causal flash attention. Paired q-tiles (bx, 31-bx): 33 iters/CTA,
// grid (16,8) = 128 CTAs = 1 wave. 512 thr, warp grid 4m x 4n. fp16 HMMA:
// S = Q K (Q frags preloaded in regs, 1 MMA/half), O += P V (1 MMA).
// cp.async double-buffered KV. smem: Q 17408 | KV 2x34816 | P 9216 | ms 1024.
// ---------------------------------------------------------------------------
#define QSTR 272
#define PSTR 144
#define KVB_K 17408
#define KVSTG (2 * KVB_K)
#define OFF_KV 17408
#define OFF_P (OFF_KV + 2 * KVSTG)   // 87040
#define OFF_MS (OFF_P + 9216)        // 96256
#define ATT_SMEM (OFF_MS + 1024)     // 97280

__global__ __launch_bounds__(512) void attn_mma(float* __restrict__ out) {
  extern __shared__ __align__(16) char smA[];
  const uint32_t sb = smem_u32(smA);
  float* msm = (float*)(smA + OFF_MS);

  const int tid = threadIdx.x, lane = tid & 31, wid = tid >> 5;
  const int wm = wid & 3, wn = wid >> 2;
  const int g = lane >> 2, tig = lane & 3;
  const int b = blockIdx.y;

  const int aRow = lane & 15;
  const int aCol = (lane >> 4) * 16;
  const int bRow = ((lane >> 4) << 3) + (lane & 7);
  const int bCol = ((lane >> 3) & 1) * 16;
  const int vRow = (lane & 7) + (((lane >> 3) & 1) << 3);
  const int vCol = (lane >> 4) * 8;
  const int rA = 16 * wm + g;

  const int ldRow = tid >> 3, ldC = tid & 7;
  const uint32_t ldDst = ldRow * QSTR + ldC * 16;
  const size_t ldSrc = (size_t)ldRow * HD + ldC * 8;

  for (int phse = 0; phse < 2; phse++) {
    const int qt = phse ? (31 - blockIdx.x) : blockIdx.x;
    const size_t qoff = ((size_t)b * TSEQ + (size_t)qt * 64) * HD;
    __syncthreads();  // prev phase fully done before Q restage
    {
      const uint4* qhp = (const uint4*)(g_qh + qoff);
#pragma unroll
      for (int it = 0; it < 2; it++) {
        int idx = tid + it * 512;
        uint32_t d = (idx >> 4) * QSTR + (idx & 15) * 16;
        *(uint4*)(smA + d) = qhp[idx];
      }
    }
    __syncthreads();  // Q staged

    // preload Q fragments into registers for the whole phase
    uint32_t qf[8][4];
#pragma unroll
    for (int c = 0; c < 8; c++)
      ldm_x4(qf[c], sb + (16 * wm + aRow) * QSTR + c * 32 + aCol);

    // prologue: KV tile 0 into buffer 0
    {
      const size_t koff = (size_t)b * TSEQ * HD;
      const uint32_t d0 = sb + OFF_KV + ldDst;
      CP16(d0, g_kh + koff + ldSrc);
      CP16(d0 + 128, g_kh + koff + ldSrc + 64);
      CP16(d0 + KVB_K, g_vh + koff + ldSrc);
      CP16(d0 + KVB_K + 128, g_vh + koff + ldSrc + 64);
      CP_COMMIT();
    }

    float O[4][4];
#pragma unroll
    for (int nt = 0; nt < 4; nt++)
#pragma unroll
      for (int r = 0; r < 4; r++) O[nt][r] = 0.f;
    float m_r[2] = {-1e30f, -1e30f}, l_r[2] = {0.f, 0.f};

    for (int kb = 0; kb <= qt; kb++) {
      const uint32_t kvb = sb + OFF_KV + (kb & 1) * KVSTG;
      if (kb < qt) {
        const size_t koff = ((size_t)b * TSEQ + (size_t)(kb + 1) * 64) * HD;
        const uint32_t ob = sb + OFF_KV + ((kb + 1) & 1) * KVSTG + ldDst;
        CP16(ob, g_kh + koff + ldSrc);
        CP16(ob + 128, g_kh + koff + ldSrc + 64);
        CP16(ob + KVB_K, g_vh + koff + ldSrc);
        CP16(ob + KVB_K + 128, g_vh + koff + ldSrc + 64);
        CP_COMMIT();
        CP_WAIT1();
      } else {
        CP_WAIT0();
      }
      __syncthreads();

      // ---- S = Q K ----
      float sfr[2][4];
#pragma unroll
      for (int nt = 0; nt < 2; nt++)
#pragma unroll
        for (int r = 0; r < 4; r++) sfr[nt][r] = 0.f;
#pragma unroll
      for (int c = 0; c < 8; c++) {
        uint32_t kh4[4];
        ldm_x4(kh4, kvb + (16 * wn + bRow) * QSTR + c * 32 + bCol);
#pragma unroll
        for (int h = 0; h < 2; h++) mma_fp16(sfr[h], qf[c], &kh4[2 * h]);
      }

      if (kb == qt) {
#pragma unroll
        for (int nt = 0; nt < 2; nt++) {
          int colRel = 16 * wn + 8 * nt + 2 * tig;
          if (colRel > rA) sfr[nt][0] = -1e30f;
          if (colRel + 1 > rA) sfr[nt][1] = -1e30f;
          if (colRel > rA + 8) sfr[nt][2] = -1e30f;
          if (colRel + 1 > rA + 8) sfr[nt][3] = -1e30f;
        }
      }

      float mxA = fmaxf(fmaxf(sfr[0][0], sfr[0][1]), fmaxf(sfr[1][0], sfr[1][1]));
      float mxB = fmaxf(fmaxf(sfr[0][2], sfr[0][3]), fmaxf(sfr[1][2], sfr[1][3]));
#pragma unroll
      for (int o = 1; o <= 2; o <<= 1) {
        mxA = fmaxf(mxA, __shfl_xor_sync(0xffffffffu, mxA, o));
        mxB = fmaxf(mxB, __shfl_xor_sync(0xffffffffu, mxB, o));
      }
      if (tig == 0) {
        msm[rA * 4 + wn] = mxA;
        msm[(rA + 8) * 4 + wn] = mxB;
      }
      __syncthreads();
      float nmA = fmaxf(m_r[0],
                        fmaxf(fmaxf(msm[rA * 4 + 0], msm[rA * 4 + 1]),
                              fmaxf(msm[rA * 4 + 2], msm[rA * 4 + 3])));
      float nmB = fmaxf(m_r[1],
                        fmaxf(fmaxf(msm[(rA + 8) * 4 + 0], msm[(rA + 8) * 4 + 1]),
                              fmaxf(msm[(rA + 8) * 4 + 2], msm[(rA + 8) * 4 + 3])));
      float corrA = __expf(m_r[0] - nmA);
      float corrB = __expf(m_r[1] - nmB);
      m_r[0] = nmA;
      m_r[1] = nmB;

      float sumA = 0.f, sumB = 0.f;
#pragma unroll
      for (int nt = 0; nt < 2; nt++) {
        float pa0 = __expf(sfr[nt][0] - nmA), pa1 = __expf(sfr[nt][1] - nmA);
        float pb0 = __expf(sfr[nt][2] - nmB), pb1 = __expf(sfr[nt][3] - nmB);
        sumA += pa0 + pa1;
        sumB += pb0 + pb1;
        int colb = (16 * wn + 8 * nt + 2 * tig) * 2;
        __half2 ha = __floats2half2_rn(pa0, pa1);
        __half2 hb = __floats2half2_rn(pb0, pb1);
        *(uint32_t*)(smA + OFF_P + rA * PSTR + colb) = *(uint32_t*)&ha;
        *(uint32_t*)(smA + OFF_P + (rA + 8) * PSTR + colb) = *(uint32_t*)&hb;
      }
#pragma unroll
      for (int o = 1; o <= 2; o <<= 1) {
        sumA += __shfl_xor_sync(0xffffffffu, sumA, o);
        sumB += __shfl_xor_sync(0xffffffffu, sumB, o);
      }
      l_r[0] = l_r[0] * corrA + sumA;
      l_r[1] = l_r[1] * corrB + sumB;
#pragma unroll
      for (int nt = 0; nt < 4; nt++) {
        O[nt][0] *= corrA;
        O[nt][1] *= corrA;
        O[nt][2] *= corrB;
        O[nt][3] *= corrB;
      }
      __syncthreads();  // P visible

      // ---- O += P V ----
#pragma unroll
      for (int ck = 0; ck < 4; ck++) {
        uint32_t pfh[4];
        ldm_x4(pfh, sb + OFF_P + (16 * wm + aRow) * PSTR + ck * 32 + aCol);
#pragma unroll
        for (int pv = 0; pv < 2; pv++) {
          uint32_t vh4[4];
          uint32_t vd = kvb + KVB_K + (16 * ck + vRow) * QSTR +
                        (32 * wn + 16 * pv + vCol) * 2;
          ldm_x4_t(vh4, vd);
#pragma unroll
          for (int h = 0; h < 2; h++) mma_fp16(O[2 * pv + h], pfh, &vh4[2 * h]);
        }
      }
      __syncthreads();  // KV/P reads done before next tile lands
    }

    // epilogue: merge per-warp l partials, normalize, write
    if (tig == 0) {
      msm[rA * 4 + wn] = l_r[0];
      msm[(rA + 8) * 4 + wn] = l_r[1];
    }
    __syncthreads();
    float liA = 1.f / (msm[rA * 4 + 0] + msm[rA * 4 + 1] + msm[rA * 4 + 2] +
                       msm[rA * 4 + 3]);
    float liB = 1.f / (msm[(rA + 8) * 4 + 0] + msm[(rA + 8) * 4 + 1] +
                       msm[(rA + 8) * 4 + 2] + msm[(rA + 8) * 4 + 3]);
    const size_t tA = (size_t)b * TSEQ + qt * 64 + rA;
#pragma unroll
    for (int nt = 0; nt < 4; nt++) {
      int col = 32 * wn + 8 * nt + 2 * tig;
      *(float2*)&out[tA * HD + col] = make_float2(O[nt][0] * liA, O[nt][1] * liA);
      *(float2*)&out[(tA + 8) * HD + col] =
          make_float2(O[nt][2] * liB, O[nt][3] * liB);
    }
  }
}

extern "C" void kernel_launch(void* const* d_in, const int* in_sizes, int n_in,
                              void* d_out, int out_size) {
  (void)in_sizes; (void)n_in; (void)out_size;
  const float* x  = (const float*)d_in[0];
  const float* Wq = (const float*)d_in[1];
  const float* Wk = (const float*)d_in[2];
  const float* Wv = (const float*)d_in[3];
  float* out = (float*)d_out;

  const int SMEMQ = 2 * NBUF_B;  // 40960 B
  cudaFuncSetAttribute(qkv_hmma, cudaFuncAttributeMaxDynamicSharedMemorySize,
                       SMEMQ);
  dim3 g1(128, 3);
  qkv_hmma<<<g1, 512, SMEMQ>>>(x, Wq, Wk, Wv);

  cudaFuncSetAttribute(attn_mma, cudaFuncAttributeMaxDynamicSharedMemorySize,
                       ATT_SMEM);
  dim3 g2(16, 8);
  attn_mma<<<g2, 512, ATT_SMEM>>>(out);
}

// round 16
// speedup vs baseline: 1.4005x; 1.4005x over previous
#include <cuda_runtime.h>
#include <cuda_fp16.h>
#include <cstdint>

#define TSEQ 2048
#define BATCH 8
#define DM 1024
#define HD 128
#define MTOT (BATCH * TSEQ)

// fp16 scratch: Q (pre-scaled by 1/sqrt(HD)), K, V.
__device__ __align__(16) __half g_qh[MTOT * HD];
__device__ __align__(16) __half g_kh[MTOT * HD];
__device__ __align__(16) __half g_vh[MTOT * HD];

__device__ __forceinline__ uint32_t smem_u32(const void* p) {
  return (uint32_t)__cvta_generic_to_shared(p);
}

__device__ __forceinline__ void mma_fp16(float* d, const uint32_t* a,
                                         const uint32_t* b) {
  asm volatile(
      "mma.sync.aligned.m16n8k16.row.col.f32.f16.f16.f32 "
      "{%0,%1,%2,%3}, {%4,%5,%6,%7}, {%8,%9}, {%0,%1,%2,%3};\n"
      : "+f"(d[0]), "+f"(d[1]), "+f"(d[2]), "+f"(d[3])
      : "r"(a[0]), "r"(a[1]), "r"(a[2]), "r"(a[3]), "r"(b[0]), "r"(b[1]));
}

__device__ __forceinline__ void ldm_x4(uint32_t* r, uint32_t addr) {
  asm volatile(
      "ldmatrix.sync.aligned.m8n8.x4.shared.b16 {%0,%1,%2,%3}, [%4];"
      : "=r"(r[0]), "=r"(r[1]), "=r"(r[2]), "=r"(r[3]) : "r"(addr));
}
__device__ __forceinline__ void ldm_x4_t(uint32_t* r, uint32_t addr) {
  asm volatile(
      "ldmatrix.sync.aligned.m8n8.x4.trans.shared.b16 {%0,%1,%2,%3}, [%4];"
      : "=r"(r[0]), "=r"(r[1]), "=r"(r[2]), "=r"(r[3]) : "r"(addr));
}

#define CP16(dst, src) \
  asm volatile("cp.async.cg.shared.global [%0], [%1], 16;" :: "r"(dst), "l"(src))
#define CP_COMMIT() asm volatile("cp.async.commit_group;" ::: "memory")
#define CP_WAIT0() asm volatile("cp.async.wait_group 0;" ::: "memory")
#define CP_WAIT1() asm volatile("cp.async.wait_group 1;" ::: "memory")

// 8 fp32 -> 8 fp16 (single)
__device__ __forceinline__ uint4 cvt8s(float4 a0, float4 a1) {
  __half2 h0 = __floats2half2_rn(a0.x, a0.y);
  __half2 h1 = __floats2half2_rn(a0.z, a0.w);
  __half2 h2 = __floats2half2_rn(a1.x, a1.y);
  __half2 h3 = __floats2half2_rn(a1.z, a1.w);
  return make_uint4(*(uint32_t*)&h0, *(uint32_t*)&h1, *(uint32_t*)&h2,
                    *(uint32_t*)&h3);
}

// ---------------------------------------------------------------------------
// Kernel 1: QKV projection (R13 measured, ~93us). Uniform fp16 HMMA:
// y = xh * W. Grid (128,3), 512 thr, BK=32, double-buffered smem, 80B stride.
// ---------------------------------------------------------------------------
#define RSTRIDE 80
#define TILE_B (128 * RSTRIDE)  // 10240
#define NBUF_B (2 * TILE_B)     // Xh, W

__global__ __launch_bounds__(512) void qkv_hmma(
    const float* __restrict__ x, const float* __restrict__ Wq,
    const float* __restrict__ Wk, const float* __restrict__ Wv) {
  extern __shared__ __align__(1024) char smem[];
  const int yid = blockIdx.y;
  const float* W = (yid == 0) ? Wq : (yid == 1 ? Wk : Wv);

  const int tid = threadIdx.x;
  const int lane = tid & 31, wid = tid >> 5;
  const int wm = wid >> 2, wn = wid & 3;
  const int m0 = blockIdx.x * 128;
  const uint32_t sb = smem_u32(smem);

  const int lrow = tid >> 2, lc = tid & 3;
  const float* aSrc = x + (size_t)(m0 + lrow) * DM + lc * 8;
  const float* bSrc = W + (size_t)lrow * DM + lc * 8;
  const uint32_t stoOff = lrow * RSTRIDE + lc * 16;

  const uint32_t aColOff = (lane >> 4) * 16;
  const uint32_t aRowB = (wm * 32 + (lane & 15)) * RSTRIDE;
  const uint32_t bRowB = (wn * 32 + ((lane >> 4) << 3) + (lane & 7)) * RSTRIDE;
  const uint32_t bColOff = ((lane >> 3) & 1) * 16;

  float acc[2][4][4];
#pragma unroll
  for (int i = 0; i < 2; i++)
#pragma unroll
    for (int j = 0; j < 4; j++)
#pragma unroll
      for (int r = 0; r < 4; r++) acc[i][j][r] = 0.f;

  float4 pA0, pA1, pB0, pB1;
  pA0 = *(const float4*)(aSrc);
  pA1 = *(const float4*)(aSrc + 4);
  pB0 = *(const float4*)(bSrc);
  pB1 = *(const float4*)(bSrc + 4);
  {
    char* p = smem + stoOff;
    *(uint4*)(p) = cvt8s(pA0, pA1);
    *(uint4*)(p + TILE_B) = cvt8s(pB0, pB1);
  }
  __syncthreads();

  for (int kt = 0; kt < 32; kt++) {
    if (kt < 31) {
      const float* a = aSrc + (kt + 1) * 32;
      const float* b = bSrc + (kt + 1) * 32;
      pA0 = *(const float4*)(a);
      pA1 = *(const float4*)(a + 4);
      pB0 = *(const float4*)(b);
      pB1 = *(const float4*)(b + 4);
    }
    const uint32_t bufBase = sb + (kt & 1) * NBUF_B;
#pragma unroll
    for (int s = 0; s < 2; s++) {
      uint32_t ah[2][4], b2[2][4];
#pragma unroll
      for (int i = 0; i < 2; i++)
        ldm_x4(ah[i], bufBase + aRowB + i * (16 * RSTRIDE) + s * 32 + aColOff);
#pragma unroll
      for (int j = 0; j < 2; j++)
        ldm_x4(b2[j], bufBase + TILE_B + bRowB + j * (16 * RSTRIDE) + s * 32 + bColOff);
#pragma unroll
      for (int i = 0; i < 2; i++)
#pragma unroll
        for (int jj = 0; jj < 4; jj++)
          mma_fp16(acc[i][jj], ah[i], &b2[jj >> 1][(jj & 1) * 2]);
    }
    if (kt < 31) {
      char* p = smem + ((kt + 1) & 1) * NBUF_B + stoOff;
      *(uint4*)(p) = cvt8s(pA0, pA1);
      *(uint4*)(p + TILE_B) = cvt8s(pB0, pB1);
    }
    __syncthreads();
  }

  const int g = lane >> 2, tig = lane & 3;
  const float qs = (yid == 0) ? 0.08838834764831845f : 1.0f;
  __half* oh = (yid == 0) ? g_qh : (yid == 1 ? g_kh : g_vh);
#pragma unroll
  for (int i = 0; i < 2; i++) {
    int r0 = m0 + wm * 32 + i * 16 + g;
#pragma unroll
    for (int jj = 0; jj < 4; jj++) {
      int col = wn * 32 + jj * 8 + 2 * tig;
      __half2 h01 = __floats2half2_rn(acc[i][jj][0] * qs, acc[i][jj][1] * qs);
      __half2 h23 = __floats2half2_rn(acc[i][jj][2] * qs, acc[i][jj][3] * qs);
      *(uint32_t*)&oh[(size_t)r0 * HD + col] = *(uint32_t*)&h01;
      *(uint32_t*)&oh[(size_t)(r0 + 8) * HD + col] = *(uint32_t*)&h23;
    }
  }
}

// ---------------------------------------------------------------------------
// Kernel 2: causal flash attention = R10's measured-good kernel minus the
// Q-lo path (single-fp16 Q, NO register preload -> regs stay ~60).
// Paired q-tiles (bx, 31-bx): 33 iters/CTA, grid (16,8) = 128 CTAs = 1 wave.
// 512 thr, warp grid 4m x 4n. S = Q K (1 MMA/half), O += P V (1 MMA).
// cp.async double-buffered KV. smem: Q 17408 | KV 2x34816 | P 9216 | ms 1024.
// ---------------------------------------------------------------------------
#define QSTR 272
#define PSTR 144
#define KVB_K 17408
#define KVSTG (2 * KVB_K)
#define OFF_KV 17408
#define OFF_P (OFF_KV + 2 * KVSTG)   // 87040
#define OFF_MS (OFF_P + 9216)        // 96256
#define ATT_SMEM (OFF_MS + 1024)     // 97280

__global__ __launch_bounds__(512) void attn_mma(float* __restrict__ out) {
  extern __shared__ __align__(16) char smA[];
  const uint32_t sb = smem_u32(smA);
  float* msm = (float*)(smA + OFF_MS);

  const int tid = threadIdx.x, lane = tid & 31, wid = tid >> 5;
  const int wm = wid & 3, wn = wid >> 2;
  const int g = lane >> 2, tig = lane & 3;
  const int b = blockIdx.y;

  const int aRow = lane & 15;
  const int aCol = (lane >> 4) * 16;
  const int bRow = ((lane >> 4) << 3) + (lane & 7);
  const int bCol = ((lane >> 3) & 1) * 16;
  const int vRow = (lane & 7) + (((lane >> 3) & 1) << 3);
  const int vCol = (lane >> 4) * 8;
  const int rA = 16 * wm + g;

  const int ldRow = tid >> 3, ldC = tid & 7;
  const uint32_t ldDst = ldRow * QSTR + ldC * 16;
  const size_t ldSrc = (size_t)ldRow * HD + ldC * 8;

  for (int phse = 0; phse < 2; phse++) {
    const int qt = phse ? (31 - blockIdx.x) : blockIdx.x;
    const size_t qoff = ((size_t)b * TSEQ + (size_t)qt * 64) * HD;
    __syncthreads();  // prev phase fully done before Q restage
    {
      const uint4* qhp = (const uint4*)(g_qh + qoff);
#pragma unroll
      for (int it = 0; it < 2; it++) {
        int idx = tid + it * 512;
        uint32_t d = (idx >> 4) * QSTR + (idx & 15) * 16;
        *(uint4*)(smA + d) = qhp[idx];
      }
    }
    // prologue: KV tile 0 into buffer 0
    {
      const size_t koff = (size_t)b * TSEQ * HD;
      const uint32_t d0 = sb + OFF_KV + ldDst;
      CP16(d0, g_kh + koff + ldSrc);
      CP16(d0 + 128, g_kh + koff + ldSrc + 64);
      CP16(d0 + KVB_K, g_vh + koff + ldSrc);
      CP16(d0 + KVB_K + 128, g_vh + koff + ldSrc + 64);
      CP_COMMIT();
    }

    float O[4][4];
#pragma unroll
    for (int nt = 0; nt < 4; nt++)
#pragma unroll
      for (int r = 0; r < 4; r++) O[nt][r] = 0.f;
    float m_r[2] = {-1e30f, -1e30f}, l_r[2] = {0.f, 0.f};

    for (int kb = 0; kb <= qt; kb++) {
      const uint32_t kvb = sb + OFF_KV + (kb & 1) * KVSTG;
      if (kb < qt) {
        const size_t koff = ((size_t)b * TSEQ + (size_t)(kb + 1) * 64) * HD;
        const uint32_t ob = sb + OFF_KV + ((kb + 1) & 1) * KVSTG + ldDst;
        CP16(ob, g_kh + koff + ldSrc);
        CP16(ob + 128, g_kh + koff + ldSrc + 64);
        CP16(ob + KVB_K, g_vh + koff + ldSrc);
        CP16(ob + KVB_K + 128, g_vh + koff + ldSrc + 64);
        CP_COMMIT();
        CP_WAIT1();
      } else {
        CP_WAIT0();
      }
      __syncthreads();  // KV (+Q on first iter) visible

      // ---- S = Q K ----
      float sfr[2][4];
#pragma unroll
      for (int nt = 0; nt < 2; nt++)
#pragma unroll
        for (int r = 0; r < 4; r++) sfr[nt][r] = 0.f;
#pragma unroll
      for (int c = 0; c < 8; c++) {
        uint32_t qh4[4], kh4[4];
        ldm_x4(qh4, sb + (16 * wm + aRow) * QSTR + c * 32 + aCol);
        ldm_x4(kh4, kvb + (16 * wn + bRow) * QSTR + c * 32 + bCol);
#pragma unroll
        for (int h = 0; h < 2; h++) mma_fp16(sfr[h], qh4, &kh4[2 * h]);
      }

      if (kb == qt) {
#pragma unroll
        for (int nt = 0; nt < 2; nt++) {
          int colRel = 16 * wn + 8 * nt + 2 * tig;
          if (colRel > rA) sfr[nt][0] = -1e30f;
          if (colRel + 1 > rA) sfr[nt][1] = -1e30f;
          if (colRel > rA + 8) sfr[nt][2] = -1e30f;
          if (colRel + 1 > rA + 8) sfr[nt][3] = -1e30f;
        }
      }

      float mxA = fmaxf(fmaxf(sfr[0][0], sfr[0][1]), fmaxf(sfr[1][0], sfr[1][1]));
      float mxB = fmaxf(fmaxf(sfr[0][2], sfr[0][3]), fmaxf(sfr[1][2], sfr[1][3]));
#pragma unroll
      for (int o = 1; o <= 2; o <<= 1) {
        mxA = fmaxf(mxA, __shfl_xor_sync(0xffffffffu, mxA, o));
        mxB = fmaxf(mxB, __shfl_xor_sync(0xffffffffu, mxB, o));
      }
      if (tig == 0) {
        msm[rA * 4 + wn] = mxA;
        msm[(rA + 8) * 4 + wn] = mxB;
      }
      __syncthreads();
      float nmA = fmaxf(m_r[0],
                        fmaxf(fmaxf(msm[rA * 4 + 0], msm[rA * 4 + 1]),
                              fmaxf(msm[rA * 4 + 2], msm[rA * 4 + 3])));
      float nmB = fmaxf(m_r[1],
                        fmaxf(fmaxf(msm[(rA + 8) * 4 + 0], msm[(rA + 8) * 4 + 1]),
                              fmaxf(msm[(rA + 8) * 4 + 2], msm[(rA + 8) * 4 + 3])));
      float corrA = __expf(m_r[0] - nmA);
      float corrB = __expf(m_r[1] - nmB);
      m_r[0] = nmA;
      m_r[1] = nmB;

      float sumA = 0.f, sumB = 0.f;
#pragma unroll
      for (int nt = 0; nt < 2; nt++) {
        float pa0 = __expf(sfr[nt][0] - nmA), pa1 = __expf(sfr[nt][1] - nmA);
        float pb0 = __expf(sfr[nt][2] - nmB), pb1 = __expf(sfr[nt][3] - nmB);
        sumA += pa0 + pa1;
        sumB += pb0 + pb1;
        int colb = (16 * wn + 8 * nt + 2 * tig) * 2;
        __half2 ha = __floats2half2_rn(pa0, pa1);
        __half2 hb = __floats2half2_rn(pb0, pb1);
        *(uint32_t*)(smA + OFF_P + rA * PSTR + colb) = *(uint32_t*)&ha;
        *(uint32_t*)(smA + OFF_P + (rA + 8) * PSTR + colb) = *(uint32_t*)&hb;
      }
#pragma unroll
      for (int o = 1; o <= 2; o <<= 1) {
        sumA += __shfl_xor_sync(0xffffffffu, sumA, o);
        sumB += __shfl_xor_sync(0xffffffffu, sumB, o);
      }
      l_r[0] = l_r[0] * corrA + sumA;
      l_r[1] = l_r[1] * corrB + sumB;
#pragma unroll
      for (int nt = 0; nt < 4; nt++) {
        O[nt][0] *= corrA;
        O[nt][1] *= corrA;
        O[nt][2] *= corrB;
        O[nt][3] *= corrB;
      }
      __syncthreads();  // P visible

      // ---- O += P V ----
#pragma unroll
      for (int ck = 0; ck < 4; ck++) {
        uint32_t pfh[4];
        ldm_x4(pfh, sb + OFF_P + (16 * wm + aRow) * PSTR + ck * 32 + aCol);
#pragma unroll
        for (int pv = 0; pv < 2; pv++) {
          uint32_t vh4[4];
          uint32_t vd = kvb + KVB_K + (16 * ck + vRow) * QSTR +
                        (32 * wn + 16 * pv + vCol) * 2;
          ldm_x4_t(vh4, vd);
#pragma unroll
          for (int h = 0; h < 2; h++) mma_fp16(O[2 * pv + h], pfh, &vh4[2 * h]);
        }
      }
      __syncthreads();  // KV/P reads done before next tile lands
    }

    // epilogue: merge per-warp l partials, normalize, write
    if (tig == 0) {
      msm[rA * 4 + wn] = l_r[0];
      msm[(rA + 8) * 4 + wn] = l_r[1];
    }
    __syncthreads();
    float liA = 1.f / (msm[rA * 4 + 0] + msm[rA * 4 + 1] + msm[rA * 4 + 2] +
                       msm[rA * 4 + 3]);
    float liB = 1.f / (msm[(rA + 8) * 4 + 0] + msm[(rA + 8) * 4 + 1] +
                       msm[(rA + 8) * 4 + 2] + msm[(rA + 8) * 4 + 3]);
    const size_t tA = (size_t)b * TSEQ + qt * 64 + rA;
#pragma unroll
    for (int nt = 0; nt < 4; nt++) {
      int col = 32 * wn + 8 * nt + 2 * tig;
      *(float2*)&out[tA * HD + col] = make_float2(O[nt][0] * liA, O[nt][1] * liA);
      *(float2*)&out[(tA + 8) * HD + col] =
          make_float2(O[nt][2] * liB, O[nt][3] * liB);
    }
  }
}

extern "C" void kernel_launch(void* const* d_in, const int* in_sizes, int n_in,
                              void* d_out, int out_size) {
  (void)in_sizes; (void)n_in; (void)out_size;
  const float* x  = (const float*)d_in[0];
  const float* Wq = (const float*)d_in[1];
  const float* Wk = (const float*)d_in[2];
  const float* Wv = (const float*)d_in[3];
  float* out = (float*)d_out;

  const int SMEMQ = 2 * NBUF_B;  // 40960 B
  cudaFuncSetAttribute(qkv_hmma, cudaFuncAttributeMaxDynamicSharedMemorySize,
                       SMEMQ);
  dim3 g1(128, 3);
  qkv_hmma<<<g1, 512, SMEMQ>>>(x, Wq, Wk, Wv);

  cudaFuncSetAttribute(attn_mma, cudaFuncAttributeMaxDynamicSharedMemorySize,
                       ATT_SMEM);
  dim3 g2(16, 8);
  attn_mma<<<g2, 512, ATT_SMEM>>>(out);
}

// round 17
// speedup vs baseline: 1.4769x; 1.0545x over previous
#include <cuda_runtime.h>
#include <cuda_fp16.h>
#include <cstdint>

#define TSEQ 2048
#define BATCH 8
#define DM 1024
#define HD 128
#define MTOT (BATCH * TSEQ)

// fp16 scratch: Q (pre-scaled by 1/sqrt(HD)), K, V.
__device__ __align__(16) __half g_qh[MTOT * HD];
__device__ __align__(16) __half g_kh[MTOT * HD];
__device__ __align__(16) __half g_vh[MTOT * HD];

__device__ __forceinline__ uint32_t smem_u32(const void* p) {
  return (uint32_t)__cvta_generic_to_shared(p);
}

__device__ __forceinline__ void mma_fp16(float* d, const uint32_t* a,
                                         const uint32_t* b) {
  asm volatile(
      "mma.sync.aligned.m16n8k16.row.col.f32.f16.f16.f32 "
      "{%0,%1,%2,%3}, {%4,%5,%6,%7}, {%8,%9}, {%0,%1,%2,%3};\n"
      : "+f"(d[0]), "+f"(d[1]), "+f"(d[2]), "+f"(d[3])
      : "r"(a[0]), "r"(a[1]), "r"(a[2]), "r"(a[3]), "r"(b[0]), "r"(b[1]));
}

__device__ __forceinline__ void ldm_x4(uint32_t* r, uint32_t addr) {
  asm volatile(
      "ldmatrix.sync.aligned.m8n8.x4.shared.b16 {%0,%1,%2,%3}, [%4];"
      : "=r"(r[0]), "=r"(r[1]), "=r"(r[2]), "=r"(r[3]) : "r"(addr));
}
__device__ __forceinline__ void ldm_x4_t(uint32_t* r, uint32_t addr) {
  asm volatile(
      "ldmatrix.sync.aligned.m8n8.x4.trans.shared.b16 {%0,%1,%2,%3}, [%4];"
      : "=r"(r[0]), "=r"(r[1]), "=r"(r[2]), "=r"(r[3]) : "r"(addr));
}

#define CP16(dst, src) \
  asm volatile("cp.async.cg.shared.global [%0], [%1], 16;" :: "r"(dst), "l"(src))
#define CP_COMMIT() asm volatile("cp.async.commit_group;" ::: "memory")
#define CP_WAIT0() asm volatile("cp.async.wait_group 0;" ::: "memory")
#define CP_WAIT1() asm volatile("cp.async.wait_group 1;" ::: "memory")

// 8 fp32 -> 8 fp16 (single)
__device__ __forceinline__ uint4 cvt8s(float4 a0, float4 a1) {
  __half2 h0 = __floats2half2_rn(a0.x, a0.y);
  __half2 h1 = __floats2half2_rn(a0.z, a0.w);
  __half2 h2 = __floats2half2_rn(a1.x, a1.y);
  __half2 h3 = __floats2half2_rn(a1.z, a1.w);
  return make_uint4(*(uint32_t*)&h0, *(uint32_t*)&h1, *(uint32_t*)&h2,
                    *(uint32_t*)&h3);
}

// ---------------------------------------------------------------------------
// Kernel 1: QKV projection, uniform fp16 HMMA, BK=64: per barrier gap each
// warp does 16 ldmatrix + 32 MMA (vs 8+16 at BK=32); 16 iters instead of 32.
// Grid (128,3), 512 thr, double-buffered smem (73728 B), 144B row stride
// (row step = 36 words ≡ 4 mod 32 -> ldmatrix conflict-free).
// Accumulation order identical to BK=32 version -> bit-identical numerics.
// ---------------------------------------------------------------------------
#define RSTRIDE 144
#define TILE_B (128 * RSTRIDE)  // 18432
#define NBUF_B (2 * TILE_B)     // 36864: Xh, W

__global__ __launch_bounds__(512) void qkv_hmma(
    const float* __restrict__ x, const float* __restrict__ Wq,
    const float* __restrict__ Wk, const float* __restrict__ Wv) {
  extern __shared__ __align__(1024) char smem[];
  const int yid = blockIdx.y;
  const float* W = (yid == 0) ? Wq : (yid == 1 ? Wk : Wv);

  const int tid = threadIdx.x;
  const int lane = tid & 31, wid = tid >> 5;
  const int wm = wid >> 2, wn = wid & 3;
  const int m0 = blockIdx.x * 128;
  const uint32_t sb = smem_u32(smem);

  // loader role: row 0..127, chunks lc and lc+4 (of 8 16B-chunks per 64-col row)
  const int lrow = tid >> 2, lc = tid & 3;
  const float* aSrc = x + (size_t)(m0 + lrow) * DM + lc * 8;
  const float* bSrc = W + (size_t)lrow * DM + lc * 8;
  const uint32_t stoOff = lrow * RSTRIDE + lc * 16;

  const uint32_t aColOff = (lane >> 4) * 16;
  const uint32_t aRowB = (wm * 32 + (lane & 15)) * RSTRIDE;
  const uint32_t bRowB = (wn * 32 + ((lane >> 4) << 3) + (lane & 7)) * RSTRIDE;
  const uint32_t bColOff = ((lane >> 3) & 1) * 16;

  float acc[2][4][4];
#pragma unroll
  for (int i = 0; i < 2; i++)
#pragma unroll
    for (int j = 0; j < 4; j++)
#pragma unroll
      for (int r = 0; r < 4; r++) acc[i][j][r] = 0.f;

  // prefetch regs: 2 chunks x (2 float4) per matrix
  float4 pA0, pA1, pA2, pA3, pB0, pB1, pB2, pB3;
  pA0 = *(const float4*)(aSrc);
  pA1 = *(const float4*)(aSrc + 4);
  pA2 = *(const float4*)(aSrc + 32);
  pA3 = *(const float4*)(aSrc + 36);
  pB0 = *(const float4*)(bSrc);
  pB1 = *(const float4*)(bSrc + 4);
  pB2 = *(const float4*)(bSrc + 32);
  pB3 = *(const float4*)(bSrc + 36);
  {
    char* p = smem + stoOff;
    *(uint4*)(p) = cvt8s(pA0, pA1);
    *(uint4*)(p + 64) = cvt8s(pA2, pA3);
    *(uint4*)(p + TILE_B) = cvt8s(pB0, pB1);
    *(uint4*)(p + TILE_B + 64) = cvt8s(pB2, pB3);
  }
  __syncthreads();

  for (int kt = 0; kt < 16; kt++) {
    if (kt < 15) {
      const float* a = aSrc + (kt + 1) * 64;
      const float* b = bSrc + (kt + 1) * 64;
      pA0 = *(const float4*)(a);
      pA1 = *(const float4*)(a + 4);
      pA2 = *(const float4*)(a + 32);
      pA3 = *(const float4*)(a + 36);
      pB0 = *(const float4*)(b);
      pB1 = *(const float4*)(b + 4);
      pB2 = *(const float4*)(b + 32);
      pB3 = *(const float4*)(b + 36);
    }
    const uint32_t bufBase = sb + (kt & 1) * NBUF_B;
#pragma unroll
    for (int s = 0; s < 4; s++) {
      uint32_t ah[2][4], b2[2][4];
#pragma unroll
      for (int i = 0; i < 2; i++)
        ldm_x4(ah[i], bufBase + aRowB + i * (16 * RSTRIDE) + s * 32 + aColOff);
#pragma unroll
      for (int j = 0; j < 2; j++)
        ldm_x4(b2[j], bufBase + TILE_B + bRowB + j * (16 * RSTRIDE) + s * 32 + bColOff);
#pragma unroll
      for (int i = 0; i < 2; i++)
#pragma unroll
        for (int jj = 0; jj < 4; jj++)
          mma_fp16(acc[i][jj], ah[i], &b2[jj >> 1][(jj & 1) * 2]);
    }
    if (kt < 15) {
      char* p = smem + ((kt + 1) & 1) * NBUF_B + stoOff;
      *(uint4*)(p) = cvt8s(pA0, pA1);
      *(uint4*)(p + 64) = cvt8s(pA2, pA3);
      *(uint4*)(p + TILE_B) = cvt8s(pB0, pB1);
      *(uint4*)(p + TILE_B + 64) = cvt8s(pB2, pB3);
    }
    __syncthreads();
  }

  const int g = lane >> 2, tig = lane & 3;
  const float qs = (yid == 0) ? 0.08838834764831845f : 1.0f;
  __half* oh = (yid == 0) ? g_qh : (yid == 1 ? g_kh : g_vh);
#pragma unroll
  for (int i = 0; i < 2; i++) {
    int r0 = m0 + wm * 32 + i * 16 + g;
#pragma unroll
    for (int jj = 0; jj < 4; jj++) {
      int col = wn * 32 + jj * 8 + 2 * tig;
      __half2 h01 = __floats2half2_rn(acc[i][jj][0] * qs, acc[i][jj][1] * qs);
      __half2 h23 = __floats2half2_rn(acc[i][jj][2] * qs, acc[i][jj][3] * qs);
      *(uint32_t*)&oh[(size_t)r0 * HD + col] = *(uint32_t*)&h01;
      *(uint32_t*)&oh[(size_t)(r0 + 8) * HD + col] = *(uint32_t*)&h23;
    }
  }
}

// ---------------------------------------------------------------------------
// Kernel 2: causal flash attention (R16 measured-good, 64.6us — unchanged).
// Paired q-tiles (bx, 31-bx): 33 iters/CTA, grid (16,8) = 128 CTAs = 1 wave.
// 512 thr, warp grid 4m x 4n. S = Q K (1 MMA/half), O += P V (1 MMA).
// cp.async double-buffered KV. smem: Q 17408 | KV 2x34816 | P 9216 | ms 1024.
// ---------------------------------------------------------------------------
#define QSTR 272
#define PSTR 144
#define KVB_K 17408
#define KVSTG (2 * KVB_K)
#define OFF_KV 17408
#define OFF_P (OFF_KV + 2 * KVSTG)   // 87040
#define OFF_MS (OFF_P + 9216)        // 96256
#define ATT_SMEM (OFF_MS + 1024)     // 97280

__global__ __launch_bounds__(512) void attn_mma(float* __restrict__ out) {
  extern __shared__ __align__(16) char smA[];
  const uint32_t sb = smem_u32(smA);
  float* msm = (float*)(smA + OFF_MS);

  const int tid = threadIdx.x, lane = tid & 31, wid = tid >> 5;
  const int wm = wid & 3, wn = wid >> 2;
  const int g = lane >> 2, tig = lane & 3;
  const int b = blockIdx.y;

  const int aRow = lane & 15;
  const int aCol = (lane >> 4) * 16;
  const int bRow = ((lane >> 4) << 3) + (lane & 7);
  const int bCol = ((lane >> 3) & 1) * 16;
  const int vRow = (lane & 7) + (((lane >> 3) & 1) << 3);
  const int vCol = (lane >> 4) * 8;
  const int rA = 16 * wm + g;

  const int ldRow = tid >> 3, ldC = tid & 7;
  const uint32_t ldDst = ldRow * QSTR + ldC * 16;
  const size_t ldSrc = (size_t)ldRow * HD + ldC * 8;

  for (int phse = 0; phse < 2; phse++) {
    const int qt = phse ? (31 - blockIdx.x) : blockIdx.x;
    const size_t qoff = ((size_t)b * TSEQ + (size_t)qt * 64) * HD;
    __syncthreads();  // prev phase fully done before Q restage
    {
      const uint4* qhp = (const uint4*)(g_qh + qoff);
#pragma unroll
      for (int it = 0; it < 2; it++) {
        int idx = tid + it * 512;
        uint32_t d = (idx >> 4) * QSTR + (idx & 15) * 16;
        *(uint4*)(smA + d) = qhp[idx];
      }
    }
    // prologue: KV tile 0 into buffer 0
    {
      const size_t koff = (size_t)b * TSEQ * HD;
      const uint32_t d0 = sb + OFF_KV + ldDst;
      CP16(d0, g_kh + koff + ldSrc);
      CP16(d0 + 128, g_kh + koff + ldSrc + 64);
      CP16(d0 + KVB_K, g_vh + koff + ldSrc);
      CP16(d0 + KVB_K + 128, g_vh + koff + ldSrc + 64);
      CP_COMMIT();
    }

    float O[4][4];
#pragma unroll
    for (int nt = 0; nt < 4; nt++)
#pragma unroll
      for (int r = 0; r < 4; r++) O[nt][r] = 0.f;
    float m_r[2] = {-1e30f, -1e30f}, l_r[2] = {0.f, 0.f};

    for (int kb = 0; kb <= qt; kb++) {
      const uint32_t kvb = sb + OFF_KV + (kb & 1) * KVSTG;
      if (kb < qt) {
        const size_t koff = ((size_t)b * TSEQ + (size_t)(kb + 1) * 64) * HD;
        const uint32_t ob = sb + OFF_KV + ((kb + 1) & 1) * KVSTG + ldDst;
        CP16(ob, g_kh + koff + ldSrc);
        CP16(ob + 128, g_kh + koff + ldSrc + 64);
        CP16(ob + KVB_K, g_vh + koff + ldSrc);
        CP16(ob + KVB_K + 128, g_vh + koff + ldSrc + 64);
        CP_COMMIT();
        CP_WAIT1();
      } else {
        CP_WAIT0();
      }
      __syncthreads();  // KV (+Q on first iter) visible

      // ---- S = Q K ----
      float sfr[2][4];
#pragma unroll
      for (int nt = 0; nt < 2; nt++)
#pragma unroll
        for (int r = 0; r < 4; r++) sfr[nt][r] = 0.f;
#pragma unroll
      for (int c = 0; c < 8; c++) {
        uint32_t qh4[4], kh4[4];
        ldm_x4(qh4, sb + (16 * wm + aRow) * QSTR + c * 32 + aCol);
        ldm_x4(kh4, kvb + (16 * wn + bRow) * QSTR + c * 32 + bCol);
#pragma unroll
        for (int h = 0; h < 2; h++) mma_fp16(sfr[h], qh4, &kh4[2 * h]);
      }

      if (kb == qt) {
#pragma unroll
        for (int nt = 0; nt < 2; nt++) {
          int colRel = 16 * wn + 8 * nt + 2 * tig;
          if (colRel > rA) sfr[nt][0] = -1e30f;
          if (colRel + 1 > rA) sfr[nt][1] = -1e30f;
          if (colRel > rA + 8) sfr[nt][2] = -1e30f;
          if (colRel + 1 > rA + 8) sfr[nt][3] = -1e30f;
        }
      }

      float mxA = fmaxf(fmaxf(sfr[0][0], sfr[0][1]), fmaxf(sfr[1][0], sfr[1][1]));
      float mxB = fmaxf(fmaxf(sfr[0][2], sfr[0][3]), fmaxf(sfr[1][2], sfr[1][3]));
#pragma unroll
      for (int o = 1; o <= 2; o <<= 1) {
        mxA = fmaxf(mxA, __shfl_xor_sync(0xffffffffu, mxA, o));
        mxB = fmaxf(mxB, __shfl_xor_sync(0xffffffffu, mxB, o));
      }
      if (tig == 0) {
        msm[rA * 4 + wn] = mxA;
        msm[(rA + 8) * 4 + wn] = mxB;
      }
      __syncthreads();
      float nmA = fmaxf(m_r[0],
                        fmaxf(fmaxf(msm[rA * 4 + 0], msm[rA * 4 + 1]),
                              fmaxf(msm[rA * 4 + 2], msm[rA * 4 + 3])));
      float nmB = fmaxf(m_r[1],
                        fmaxf(fmaxf(msm[(rA + 8) * 4 + 0], msm[(rA + 8) * 4 + 1]),
                              fmaxf(msm[(rA + 8) * 4 + 2], msm[(rA + 8) * 4 + 3])));
      float corrA = __expf(m_r[0] - nmA);
      float corrB = __expf(m_r[1] - nmB);
      m_r[0] = nmA;
      m_r[1] = nmB;

      float sumA = 0.f, sumB = 0.f;
#pragma unroll
      for (int nt = 0; nt < 2; nt++) {
        float pa0 = __expf(sfr[nt][0] - nmA), pa1 = __expf(sfr[nt][1] - nmA);
        float pb0 = __expf(sfr[nt][2] - nmB), pb1 = __expf(sfr[nt][3] - nmB);
        sumA += pa0 + pa1;
        sumB += pb0 + pb1;
        int colb = (16 * wn + 8 * nt + 2 * tig) * 2;
        __half2 ha = __floats2half2_rn(pa0, pa1);
        __half2 hb = __floats2half2_rn(pb0, pb1);
        *(uint32_t*)(smA + OFF_P + rA * PSTR + colb) = *(uint32_t*)&ha;
        *(uint32_t*)(smA + OFF_P + (rA + 8) * PSTR + colb) = *(uint32_t*)&hb;
      }
#pragma unroll
      for (int o = 1; o <= 2; o <<= 1) {
        sumA += __shfl_xor_sync(0xffffffffu, sumA, o);
        sumB += __shfl_xor_sync(0xffffffffu, sumB, o);
      }
      l_r[0] = l_r[0] * corrA + sumA;
      l_r[1] = l_r[1] * corrB + sumB;
#pragma unroll
      for (int nt = 0; nt < 4; nt++) {
        O[nt][0] *= corrA;
        O[nt][1] *= corrA;
        O[nt][2] *= corrB;
        O[nt][3] *= corrB;
      }
      __syncthreads();  // P visible

      // ---- O += P V ----
#pragma unroll
      for (int ck = 0; ck < 4; ck++) {
        uint32_t pfh[4];
        ldm_x4(pfh, sb + OFF_P + (16 * wm + aRow) * PSTR + ck * 32 + aCol);
#pragma unroll
        for (int pv = 0; pv < 2; pv++) {
          uint32_t vh4[4];
          uint32_t vd = kvb + KVB_K + (16 * ck + vRow) * QSTR +
                        (32 * wn + 16 * pv + vCol) * 2;
          ldm_x4_t(vh4, vd);
#pragma unroll
          for (int h = 0; h < 2; h++) mma_fp16(O[2 * pv + h], pfh, &vh4[2 * h]);
        }
      }
      __syncthreads();  // KV/P reads done before next tile lands
    }

    // epilogue: merge per-warp l partials, normalize, write
    if (tig == 0) {
      msm[rA * 4 + wn] = l_r[0];
      msm[(rA + 8) * 4 + wn] = l_r[1];
    }
    __syncthreads();
    float liA = 1.f / (msm[rA * 4 + 0] + msm[rA * 4 + 1] + msm[rA * 4 + 2] +
                       msm[rA * 4 + 3]);
    float liB = 1.f / (msm[(rA + 8) * 4 + 0] + msm[(rA + 8) * 4 + 1] +
                       msm[(rA + 8) * 4 + 2] + msm[(rA + 8) * 4 + 3]);
    const size_t tA = (size_t)b * TSEQ + qt * 64 + rA;
#pragma unroll
    for (int nt = 0; nt < 4; nt++) {
      int col = 32 * wn + 8 * nt + 2 * tig;
      *(float2*)&out[tA * HD + col] = make_float2(O[nt][0] * liA, O[nt][1] * liA);
      *(float2*)&out[(tA + 8) * HD + col] =
          make_float2(O[nt][2] * liB, O[nt][3] * liB);
    }
  }
}

extern "C" void kernel_launch(void* const* d_in, const int* in_sizes, int n_in,
                              void* d_out, int out_size) {
  (void)in_sizes; (void)n_in; (void)out_size;
  const float* x  = (const float*)d_in[0];
  const float* Wq = (const float*)d_in[1];
  const float* Wk = (const float*)d_in[2];
  const float* Wv = (const float*)d_in[3];
  float* out = (float*)d_out;

  const int SMEMQ = 2 * NBUF_B;  // 73728 B
  cudaFuncSetAttribute(qkv_hmma, cudaFuncAttributeMaxDynamicSharedMemorySize,
                       SMEMQ);
  dim3 g1(128, 3);
  qkv_hmma<<<g1, 512, SMEMQ>>>(x, Wq, Wk, Wv);

  cudaFuncSetAttribute(attn_mma, cudaFuncAttributeMaxDynamicSharedMemorySize,
                       ATT_SMEM);
  dim3 g2(16, 8);
  attn_mma<<<g2, 512, ATT_SMEM>>>(out);
}